// round 10
// baseline (speedup 1.0000x reference)
#include <cuda_runtime.h>

// ADI diffusion, fully fused per-step kernel.
// B=16, C=8, S=128. 10 steps of [mix, x-half, y-full, x-half].
//
// Numerics: the reference's (denom+EPS) Thomas == Thomas on the system with
// diagonal b+1e-6. Off-diag/diag ratio ~1e-3, so the truncated Neumann series
// x = (I + N + N^2 + N^3) B^-1 d  (N = -B^-1 A_off) is exact to ~1e-11/sweep.
// For the y direction we expand the series in closed form as a 7-tap stencil
// along h (radius 3), which makes the y solve TILE-LOCAL and lets us fuse
// [y | x-half | mix | x-half] into a single kernel per time step:
//   launches: 1 (mix+x) + 9 (y+x+mix+x) + 1 (y+x) = 11
//   u round-trips per step: 1 (was 2).
// Halo reads + tile writes would race in place -> ping-pong via an 8MB
// __device__ scratch buffer.

#define S_DIM 128
#define C_DIM 8
#define B_DIM 16
#define HT 8
#define EPSF 1e-6f
#define FULLMASK 0xffffffffu

__device__ float g_scratch[B_DIM * C_DIM * S_DIM * S_DIM];  // 8 MB ping buffer

// ---------------- float4 helpers ----------------
__device__ __forceinline__ float4 f4add(float4 a, float4 b) {
    return make_float4(a.x + b.x, a.y + b.y, a.z + b.z, a.w + b.w);
}
__device__ __forceinline__ float4 f4mul(float4 a, float4 b) {
    return make_float4(a.x * b.x, a.y * b.y, a.z * b.z, a.w * b.w);
}
__device__ __forceinline__ float4 f4fma(float4 a, float4 b, float4 c) {
    return make_float4(fmaf(a.x, b.x, c.x), fmaf(a.y, b.y, c.y),
                       fmaf(a.z, b.z, c.z), fmaf(a.w, b.w, c.w));
}
__device__ __forceinline__ float4 f4fmas(float s, float4 b, float4 c) {
    return make_float4(fmaf(s, b.x, c.x), fmaf(s, b.y, c.y),
                       fmaf(s, b.z, c.z), fmaf(s, b.w, c.w));
}
__device__ __forceinline__ float4 f4adds(float4 a, float s) {
    return make_float4(a.x + s, a.y + s, a.z + s, a.w + s);
}

// clip(base + t*tc, eps, 10) * scale, componentwise
__device__ __forceinline__ float4 f4coeff(float4 b4, float4 t4, float t,
                                          float scale) {
    float4 r;
    r.x = fminf(fmaxf(fmaf(t4.x, t, b4.x), EPSF), 10.0f) * scale;
    r.y = fminf(fmaxf(fmaf(t4.y, t, b4.y), EPSF), 10.0f) * scale;
    r.z = fminf(fmaxf(fmaf(t4.z, t, b4.z), EPSF), 10.0f) * scale;
    r.w = fminf(fmaxf(fmaf(t4.w, t, b4.w), EPSF), 10.0f) * scale;
    return r;
}

// ---------------- warp Neumann solve (x direction) ----------------
__device__ __forceinline__ void neumann_line(const float co[4], float d[4],
                                             int lane) {
    float w[4], y[4], acc[4];
#pragma unroll
    for (int r = 0; r < 4; r++) {
        int i = lane * 4 + r;
        float cr = co[r];
        float b = (i == 0 || i == S_DIM - 1) ? (1.0f + cr) : (1.0f + 2.0f * cr);
        b += EPSF;
        float g = __fdividef(1.0f, b);
        w[r] = cr * g;
        y[r] = d[r] * g;
        acc[r] = y[r];
    }
#pragma unroll
    for (int k = 0; k < 3; k++) {
        float up = __shfl_up_sync(FULLMASK, y[3], 1);
        float dn = __shfl_down_sync(FULLMASK, y[0], 1);
        if (lane == 0) up = 0.0f;
        if (lane == 31) dn = 0.0f;
        float n0 = w[0] * (up + y[1]);
        float n1 = w[1] * (y[0] + y[2]);
        float n2 = w[2] * (y[1] + y[3]);
        float n3 = w[3] * (y[2] + dn);
        y[0] = n0; y[1] = n1; y[2] = n2; y[3] = n3;
        acc[0] += n0; acc[1] += n1; acc[2] += n2; acc[3] += n3;
    }
#pragma unroll
    for (int r = 0; r < 4; r++) d[r] = acc[r];
}

__device__ __forceinline__ void solve_x4(float4 co4, float4& dd, int lane) {
    float co[4] = {co4.x, co4.y, co4.z, co4.w};
    float d[4] = {dd.x, dd.y, dd.z, dd.w};
    neumann_line(co, d, lane);
    dd = make_float4(d[0], d[1], d[2], d[3]);
}

// ---------------- 7-tap y operator ----------------
// out[h] = W0*y0[h] + sum_{j=1..3} (Wmj*y0[h-j] + Wpj*y0[h+j]),
// weights from p_j = w[h+j]:
//   W0  = 1 + p0(pm1+pp1)
//   W±1 = p0(1 + p0(pm1+pp1) + p±1 p±2)
//   W±2 = p0 p±1 ;  W±3 = p0 p±1 p±2
__device__ __forceinline__ float4 y_7tap(const float4* __restrict__ sy0,
                                         const float4* __restrict__ sw,
                                         int c, int hh, int lane) {
    int by = (c * 14 + hh + 3) * 32 + lane;  // sy0 rows: hg = h0-3+hr
    int bw = (c * 12 + hh + 2) * 32 + lane;  // sw rows:  hg = h0-2+hs
    float4 P0 = sw[bw - 64], P1 = sw[bw - 32], P2 = sw[bw];
    float4 P3 = sw[bw + 32], P4 = sw[bw + 64];
    float4 g = f4mul(P2, f4add(P1, P3));
    float4 one_g = f4adds(g, 1.0f);
    float4 Wm1 = f4mul(P2, f4fma(P1, P0, one_g));
    float4 Wp1 = f4mul(P2, f4fma(P3, P4, one_g));
    float4 Wm2 = f4mul(P2, P1);
    float4 Wp2 = f4mul(P2, P3);
    float4 Wm3 = f4mul(Wm2, P0);
    float4 Wp3 = f4mul(Wp2, P4);
    float4 acc = f4mul(one_g, sy0[by]);
    acc = f4fma(Wm1, sy0[by - 32], acc);
    acc = f4fma(Wp1, sy0[by + 32], acc);
    acc = f4fma(Wm2, sy0[by - 64], acc);
    acc = f4fma(Wp2, sy0[by + 64], acc);
    acc = f4fma(Wm3, sy0[by - 96], acc);
    acc = f4fma(Wp3, sy0[by + 96], acc);
    return acc;
}

// ---------------- fused step kernel ----------------
// Block = (b, 8-row h-tile) x all 8 channels. 512 threads = 16 warps.
// Warp w -> channel c=w>>1, rows hh=(w&1)*4..+3; lane owns w-elems 4l..4l+3.
// Phases: stage y0/w halo -> 7-tap y -> x-solve -> [mix -> x-solve] -> store.
// smem: sy0[8][14][32]f4 (56KB) | sw[8][12][32]f4 (48KB, aliased by sY) | sM.

template <bool DO_MIX>
__global__ void __launch_bounds__(512, 2) k_step(
    const float* __restrict__ src, float* __restrict__ dst,
    const float* __restrict__ M,
    const float* __restrict__ ab, const float* __restrict__ atc,
    const float* __restrict__ bb, const float* __restrict__ btc,
    float t_y, float t_x) {
    extern __shared__ float4 smem4[];
    float4* sy0 = smem4;           // 3584 f4
    float4* sw = smem4 + 3584;     // 3072 f4
    float4* sY = sw;               // alias (2048 f4 used, after taps done)
    float* sM = (float*)(smem4 + 3584 + 3072);

    int tid = threadIdx.x, lane = tid & 31, wrp = tid >> 5;
    int b = blockIdx.x, h0 = blockIdx.y * HT;
    int c = wrp >> 1;

    if (DO_MIX && tid < 64) sM[tid] = M[tid];

    const float4* srcf4 = (const float4*)src;
    const float4* bbf4 = (const float4*)bb;
    const float4* btf4 = (const float4*)btc;

    // ---- Phase 0: stage y0 = u*inv and w = co*inv for halo rows ----
#pragma unroll
    for (int s = 0; s < 7; s++) {
        int e = tid + s * 512;               // 3584 f4: [c][hr:14][wg:32]
        int cc = e / 448;
        int r = e - cc * 448;
        int hr = r >> 5, wg = r & 31;
        int hg = h0 - 3 + hr;
        float4 y0 = make_float4(0.f, 0.f, 0.f, 0.f);
        float4 wv = make_float4(0.f, 0.f, 0.f, 0.f);
        if (hg >= 0 && hg < S_DIM) {
            float4 u4 = srcf4[((b * C_DIM + cc) * S_DIM + hg) * 32 + wg];
            int gc = (cc * S_DIM + hg) * 32 + wg;
            float4 co = f4coeff(bbf4[gc], btf4[gc], t_y, 0.001f);  // DT/DY^2
            float edgef = (hg == 0 || hg == S_DIM - 1) ? 1.0f : 2.0f;
            float bd, inv;
            bd = fmaf(edgef, co.x, 1.0f) + EPSF; inv = __fdividef(1.0f, bd);
            y0.x = u4.x * inv; wv.x = co.x * inv;
            bd = fmaf(edgef, co.y, 1.0f) + EPSF; inv = __fdividef(1.0f, bd);
            y0.y = u4.y * inv; wv.y = co.y * inv;
            bd = fmaf(edgef, co.z, 1.0f) + EPSF; inv = __fdividef(1.0f, bd);
            y0.z = u4.z * inv; wv.z = co.z * inv;
            bd = fmaf(edgef, co.w, 1.0f) + EPSF; inv = __fdividef(1.0f, bd);
            y0.w = u4.w * inv; wv.w = co.w * inv;
        }
        sy0[e] = y0;
        if (hr >= 1 && hr <= 12) sw[(cc * 12 + (hr - 1)) * 32 + wg] = wv;
    }
    __syncthreads();

    // ---- Phase 1: y 7-tap into registers ----
    float4 d4[4];
#pragma unroll
    for (int i = 0; i < 4; i++) {
        int hh = (wrp & 1) * 4 + i;
        d4[i] = y_7tap(sy0, sw, c, hh, lane);
    }

    // ---- Phase 2: x half-step (alpha at t_x) ----
    const float4* abf4 = (const float4*)ab;
    const float4* atf4 = (const float4*)atc;
#pragma unroll
    for (int i = 0; i < 4; i++) {
        int hh = (wrp & 1) * 4 + i;
        int gc = (c * S_DIM + h0 + hh) * 32 + lane;
        float4 co = f4coeff(abf4[gc], atf4[gc], t_x, 0.0005f);  // half/DX^2
        solve_x4(co, d4[i], lane);
    }

    float4* dstf4 = (float4*)dst;
    if (DO_MIX) {
        __syncthreads();  // all tap reads of sw done -> safe to alias with sY
#pragma unroll
        for (int i = 0; i < 4; i++) {
            int hh = (wrp & 1) * 4 + i;
            sY[(c * 8 + hh) * 32 + lane] = d4[i];
        }
        __syncthreads();
        // ---- Phase 3: channel mix ----
#pragma unroll
        for (int i = 0; i < 4; i++) {
            int hh = (wrp & 1) * 4 + i;
            float4 acc = make_float4(0.f, 0.f, 0.f, 0.f);
#pragma unroll
            for (int cc = 0; cc < 8; cc++)
                acc = f4fmas(sM[c * 8 + cc], sY[(cc * 8 + hh) * 32 + lane],
                             acc);
            d4[i] = acc;
        }
        // ---- Phase 4: leading x half-step of next step (same t_x) ----
#pragma unroll
        for (int i = 0; i < 4; i++) {
            int hh = (wrp & 1) * 4 + i;
            int gc = (c * S_DIM + h0 + hh) * 32 + lane;
            float4 co = f4coeff(abf4[gc], atf4[gc], t_x, 0.0005f);
            solve_x4(co, d4[i], lane);
            dstf4[((b * C_DIM + c) * S_DIM + h0 + hh) * 32 + lane] = d4[i];
        }
    } else {
#pragma unroll
        for (int i = 0; i < 4; i++) {
            int hh = (wrp & 1) * 4 + i;
            dstf4[((b * C_DIM + c) * S_DIM + h0 + hh) * 32 + lane] = d4[i];
        }
    }
}

// ---------------- initial mix + x half-step (t=0) ----------------
#define XPITCH 132
__global__ void __launch_bounds__(512) k_mix_x(
    const float* __restrict__ u_in, const float* __restrict__ M,
    const float* __restrict__ ab, const float* __restrict__ atc,
    float* __restrict__ u_out, float t) {
    __shared__ __align__(16) float sx[16 * XPITCH];
    __shared__ float sM[64];
    int tid = threadIdx.x, lane = tid & 31, w = tid >> 5;
    int b = blockIdx.x, h0 = blockIdx.y * 2;
    int c = w >> 1, hh = w & 1, h = h0 + hh;
    if (tid < 64) sM[tid] = M[tid];
    int rowbase = (((b * C_DIM + c) * S_DIM) + h) * S_DIM;
    int crowbase = ((c * S_DIM) + h) * S_DIM;
    float4 u4 = *reinterpret_cast<const float4*>(u_in + rowbase + 4 * lane);
    *reinterpret_cast<float4*>(&sx[w * XPITCH + 4 * lane]) = u4;
    float4 co = f4coeff(
        *reinterpret_cast<const float4*>(ab + crowbase + 4 * lane),
        *reinterpret_cast<const float4*>(atc + crowbase + 4 * lane), t,
        0.0005f);
    __syncthreads();
    float4 d = make_float4(0.f, 0.f, 0.f, 0.f);
#pragma unroll
    for (int cc = 0; cc < 8; cc++) {
        float m = sM[c * 8 + cc];
        float4 s4 = *reinterpret_cast<const float4*>(
            &sx[(cc * 2 + hh) * XPITCH + 4 * lane]);
        d = f4fmas(m, s4, d);
    }
    solve_x4(co, d, lane);
    *reinterpret_cast<float4*>(u_out + rowbase + 4 * lane) = d;
}

// ---------------- Launch ----------------

extern "C" void kernel_launch(void* const* d_in, const int* in_sizes, int n_in,
                              void* d_out, int out_size) {
    const float* u = (const float*)d_in[0];
    const float* ab = (const float*)d_in[1];
    const float* bb = (const float*)d_in[2];
    const float* atc = (const float*)d_in[3];
    const float* btc = (const float*)d_in[4];
    const float* M = (const float*)d_in[5];
    float* out = (float*)d_out;

    void* sp = nullptr;
    cudaGetSymbolAddress(&sp, g_scratch);
    float* scr = (float*)sp;

    const int SMEMB = (3584 + 3072) * 16 + 256;  // 106752 B
    cudaFuncSetAttribute(k_step<true>,
                         cudaFuncAttributeMaxDynamicSharedMemorySize, SMEMB);
    cudaFuncSetAttribute(k_step<false>,
                         cudaFuncAttributeMaxDynamicSharedMemorySize, SMEMB);

    dim3 gx(B_DIM, S_DIM / 2);    // 1024 blocks
    dim3 gs(B_DIM, S_DIM / HT);   // 16 x 16 = 256 blocks

    const double DTd = 0.001, halfd = 0.0005;

    // step 0 head: mix + x-half at t=0 -> out
    k_mix_x<<<gx, 512>>>(u, M, ab, atc, out, 0.0f);
    // steps: y(t_y) + x(t_x) [+ mix + x(t_x)], ping-pong out <-> scratch
    for (int k = 0; k < 10; k++) {
        float ty = (float)(k * DTd + halfd);
        float tx = (float)((k + 1) * DTd);
        const float* s = (k % 2 == 0) ? out : scr;
        float* d = (k % 2 == 0) ? scr : out;
        if (k < 9)
            k_step<true><<<gs, 512, SMEMB>>>(s, d, M, ab, atc, bb, btc, ty, tx);
        else
            k_step<false><<<gs, 512, SMEMB>>>(s, d, M, ab, atc, bb, btc, ty,
                                              tx);
    }
    // k=9 is odd -> final write landed in `out` (d_out). Done.
}